// round 7
// baseline (speedup 1.0000x reference)
#include <cuda_runtime.h>

// conv2d 4096x4096 (fp32) * 15x15 VALID + bias -> 4082x4082 (fp32)
// R5: phase-shifted dual accumulators -> zero pack instructions.
//     Even-kx taps  -> accA[j] = (o_{2j},   o_{2j+1}) += w_{2c}   * P[j+c]
//     Odd-kx  taps  -> accB[j] = (o_{2j-1}, o_{2j}  ) += w_{2c+1} * P[j+c]
//     P pairs come free from ulonglong2-reinterpreted float4 smem loads.
//     occupancy 3 blocks/SM for latency hiding.

#define H 4096
#define W 4096
#define KH 15
#define KW 15
#define OH 4082
#define OW 4082

#define BX 192          // output tile width  (16 threads * RX=12)
#define BY 16           // output tile height
#define NT 256
#define RX 12           // 48B per-lane stride -> odd multiple of 16B -> conflict-free

#define IN_H (BY + KH - 1)          // 30
#define SROW 208                    // 192+14 -> pad to 208 (52 float4)

typedef unsigned long long ull;

__device__ __forceinline__ ull pack2(float lo, float hi) {
    ull r;
    asm("mov.b64 %0, {%1, %2};" : "=l"(r) : "f"(lo), "f"(hi));
    return r;
}
__device__ __forceinline__ void unpack2(ull v, float& lo, float& hi) {
    asm("mov.b64 {%0, %1}, %2;" : "=f"(lo), "=f"(hi) : "l"(v));
}
__device__ __forceinline__ ull fma2(ull a, ull b, ull c) {
    ull d;
    asm("fma.rn.f32x2 %0, %1, %2, %3;" : "=l"(d) : "l"(a), "l"(b), "l"(c));
    return d;
}

__global__ __launch_bounds__(NT, 3)
void conv2d_r5_kernel(const float* __restrict__ X,
                      const float* __restrict__ Wt,
                      const float* __restrict__ bias,
                      float* __restrict__ out)
{
    __shared__ __align__(16) float sX[IN_H][SROW];
    __shared__ __align__(16) ull  sWp[KH * 16];   // (w,w) pairs, row-padded to 16

    const int tid = threadIdx.x;
    const int bx = blockIdx.x * BX;
    const int by = blockIdx.y * BY;

    // ---- stage weight pairs (duplicated into 64-bit lanes) ----
    if (tid < KH * 16) {
        int r = tid >> 4, c = tid & 15;
        float w = (c < KW) ? Wt[r * KW + c] : 0.f;
        sWp[tid] = pack2(w, w);
    }

    // ---- stage input tile: 30 rows x 208 cols, float4, guarded ----
    const int NV = IN_H * (SROW / 4);     // 30*52 = 1560
    for (int idx = tid; idx < NV; idx += NT) {
        int r  = idx / (SROW / 4);
        int c4 = idx - r * (SROW / 4);
        int gr = by + r;
        int gc = bx + c4 * 4;
        float4 v = make_float4(0.f, 0.f, 0.f, 0.f);
        if (gr < H) {
            const float* src = X + (long)gr * W + gc;
            if (gc + 3 < W) v = *(const float4*)src;
            else {
                if (gc + 0 < W) v.x = src[0];
                if (gc + 1 < W) v.y = src[1];
                if (gc + 2 < W) v.z = src[2];
                if (gc + 3 < W) v.w = src[3];
            }
        }
        *(float4*)&sX[r][c4 * 4] = v;
    }
    __syncthreads();

    const int tx = tid & 15;
    const int ty = tid >> 4;
    const int ox = tx * RX;               // 48B stride: conflict-free, 16B aligned

    ull accA[6];                          // (o_{2j}, o_{2j+1})
    ull accB[7];                          // (o_{2j-1}, o_{2j});  B[0].lo, B[6].hi unused
    #pragma unroll
    for (int j = 0; j < 6; ++j) accA[j] = 0ull;   // +0.0f bits
    #pragma unroll
    for (int j = 0; j < 7; ++j) accB[j] = 0ull;

    #pragma unroll 1
    for (int ky = 0; ky < KH; ++ky) {
        // 7 LDS.128 -> 14 aligned even pairs P[0..13], zero pack cost
        const ulonglong2* row = (const ulonglong2*)&sX[ty + ky][ox];
        ull P[14];
        #pragma unroll
        for (int t = 0; t < 7; ++t) {
            ulonglong2 v = row[t];
            P[2 * t]     = v.x;   // (x_{8t..}, pair low)
            P[2 * t + 1] = v.y;
        }

        const ull* wrow = &sWp[ky * 16];
        #pragma unroll
        for (int c = 0; c < 8; ++c) {
            const ulonglong2 wp = *(const ulonglong2*)(wrow + 2 * c); // w_{2c}, w_{2c+1}
            // even tap a=2c: accA[j] += w * P[j+c]
            #pragma unroll
            for (int j = 0; j < 6; ++j)
                accA[j] = fma2(wp.x, P[j + c], accA[j]);
            // odd tap a=2c+1: accB[j] += w * P[j+c]
            if (c < 7) {
                #pragma unroll
                for (int j = 0; j < 7; ++j)
                    accB[j] = fma2(wp.y, P[j + c], accB[j]);
            }
        }
    }

    // ---- epilogue: recombine phases, add bias, guarded float2 stores ----
    const float b0 = bias[0];
    const int orow = by + ty;
    if (orow < OH) {
        float* orp = out + (long)orow * OW;
        float alo[6], ahi[6], blo[7], bhi[7];
        #pragma unroll
        for (int j = 0; j < 6; ++j) unpack2(accA[j], alo[j], ahi[j]);
        #pragma unroll
        for (int j = 0; j < 7; ++j) unpack2(accB[j], blo[j], bhi[j]);
        #pragma unroll
        for (int j = 0; j < 6; ++j) {
            int ocol = bx + ox + 2 * j;     // even; OW even -> pair fully in or out
            if (ocol < OW) {
                float2 st;
                st.x = alo[j] + bhi[j]     + b0;   // o_{2j}
                st.y = ahi[j] + blo[j + 1] + b0;   // o_{2j+1}
                *(float2*)(orp + ocol) = st;
            }
        }
    }
}

extern "C" void kernel_launch(void* const* d_in, const int* in_sizes, int n_in,
                              void* d_out, int out_size)
{
    const float* X  = (const float*)d_in[0];
    const float* Wt = (const float*)d_in[1];
    const float* bs = (const float*)d_in[2];
    float* out = (float*)d_out;

    dim3 grid((OW + BX - 1) / BX, (OH + BY - 1) / BY);   // 22 x 256
    conv2d_r5_kernel<<<grid, NT>>>(X, Wt, bs, out);
}

// round 8
// speedup vs baseline: 1.0379x; 1.0379x over previous
#include <cuda_runtime.h>

// conv2d 4096x4096 (fp32) * 15x15 VALID + bias -> 4082x4082 (fp32)
// R8: R5 phase-shifted dual-accumulator FFMA2 kernel + occupancy push:
//     __launch_bounds__(256,4) (64-reg cap) with a rolling LDS window
//     (preload v0..v3, inject v4/v5/v6 at c=2/4/6) to fit the cap.

#define H 4096
#define W 4096
#define KH 15
#define KW 15
#define OH 4082
#define OW 4082

#define BX 192          // output tile width  (16 threads * RX=12)
#define BY 16           // output tile height
#define NT 256
#define RX 12           // 48B per-lane stride -> odd multiple of 16B -> conflict-free

#define IN_H (BY + KH - 1)          // 30
#define SROW 208                    // 192+14 -> pad to 208 (52 float4)

typedef unsigned long long ull;

__device__ __forceinline__ ull pack2(float lo, float hi) {
    ull r;
    asm("mov.b64 %0, {%1, %2};" : "=l"(r) : "f"(lo), "f"(hi));
    return r;
}
__device__ __forceinline__ void unpack2(ull v, float& lo, float& hi) {
    asm("mov.b64 {%0, %1}, %2;" : "=f"(lo), "=f"(hi) : "l"(v));
}
__device__ __forceinline__ ull fma2(ull a, ull b, ull c) {
    ull d;
    asm("fma.rn.f32x2 %0, %1, %2, %3;" : "=l"(d) : "l"(a), "l"(b), "l"(c));
    return d;
}

__global__ __launch_bounds__(NT, 4)
void conv2d_r8_kernel(const float* __restrict__ X,
                      const float* __restrict__ Wt,
                      const float* __restrict__ bias,
                      float* __restrict__ out)
{
    __shared__ __align__(16) float sX[IN_H][SROW];
    __shared__ __align__(16) ull  sWp[KH * 16];   // (w,w) pairs, row-padded to 16

    const int tid = threadIdx.x;
    const int bx = blockIdx.x * BX;
    const int by = blockIdx.y * BY;

    // ---- stage weight pairs (duplicated into 64-bit lanes) ----
    if (tid < KH * 16) {
        int r = tid >> 4, c = tid & 15;
        float w = (c < KW) ? Wt[r * KW + c] : 0.f;
        sWp[tid] = pack2(w, w);
    }

    // ---- stage input tile: 30 rows x 208 cols, float4, guarded ----
    const int NV = IN_H * (SROW / 4);     // 30*52 = 1560
    for (int idx = tid; idx < NV; idx += NT) {
        int r  = idx / (SROW / 4);
        int c4 = idx - r * (SROW / 4);
        int gr = by + r;
        int gc = bx + c4 * 4;
        float4 v = make_float4(0.f, 0.f, 0.f, 0.f);
        if (gr < H) {
            const float* src = X + (long)gr * W + gc;
            if (gc + 3 < W) v = *(const float4*)src;
            else {
                if (gc + 0 < W) v.x = src[0];
                if (gc + 1 < W) v.y = src[1];
                if (gc + 2 < W) v.z = src[2];
                if (gc + 3 < W) v.w = src[3];
            }
        }
        *(float4*)&sX[r][c4 * 4] = v;
    }
    __syncthreads();

    const int tx = tid & 15;
    const int ty = tid >> 4;
    const int ox = tx * RX;               // 48B stride: conflict-free, 16B aligned

    ull accA[6];                          // (o_{2j}, o_{2j+1})
    ull accB[7];                          // (o_{2j-1}, o_{2j});  B[0].lo, B[6].hi unused
    #pragma unroll
    for (int j = 0; j < 6; ++j) accA[j] = 0ull;
    #pragma unroll
    for (int j = 0; j < 7; ++j) accB[j] = 0ull;

    #pragma unroll 1
    for (int ky = 0; ky < KH; ++ky) {
        const ulonglong2* row = (const ulonglong2*)&sX[ty + ky][ox];
        const ulonglong2* wrow = (const ulonglong2*)&sWp[ky * 16];

        // rolling window: P[2t]=v[t].x, P[2t+1]=v[t].y
        ulonglong2 v[7];
        v[0] = row[0]; v[1] = row[1]; v[2] = row[2]; v[3] = row[3];

        #pragma unroll
        for (int c = 0; c < 8; ++c) {
            if (c == 2) v[4] = row[4];
            if (c == 4) v[5] = row[5];
            if (c == 6) v[6] = row[6];
            const ulonglong2 wp = wrow[c];    // (w_{2c}, w_{2c+1}) duplicated pairs
            // even tap a=2c: accA[j] += w * P[j+c], j=0..5
            #pragma unroll
            for (int j = 0; j < 6; ++j) {
                const int p = j + c;
                const ull Pp = (p & 1) ? v[p >> 1].y : v[p >> 1].x;
                accA[j] = fma2(wp.x, Pp, accA[j]);
            }
            // odd tap a=2c+1: accB[j] += w * P[j+c], j=0..6
            if (c < 7) {
                #pragma unroll
                for (int j = 0; j < 7; ++j) {
                    const int p = j + c;
                    const ull Pp = (p & 1) ? v[p >> 1].y : v[p >> 1].x;
                    accB[j] = fma2(wp.y, Pp, accB[j]);
                }
            }
        }
    }

    // ---- epilogue: recombine phases, add bias, guarded float2 stores ----
    const float b0 = bias[0];
    const int orow = by + ty;
    if (orow < OH) {
        float* orp = out + (long)orow * OW;
        float alo[6], ahi[6], blo[7], bhi[7];
        #pragma unroll
        for (int j = 0; j < 6; ++j) unpack2(accA[j], alo[j], ahi[j]);
        #pragma unroll
        for (int j = 0; j < 7; ++j) unpack2(accB[j], blo[j], bhi[j]);
        #pragma unroll
        for (int j = 0; j < 6; ++j) {
            int ocol = bx + ox + 2 * j;     // even; OW even -> pair fully in or out
            if (ocol < OW) {
                float2 st;
                st.x = alo[j] + bhi[j]     + b0;   // o_{2j}
                st.y = ahi[j] + blo[j + 1] + b0;   // o_{2j+1}
                *(float2*)(orp + ocol) = st;
            }
        }
    }
}

extern "C" void kernel_launch(void* const* d_in, const int* in_sizes, int n_in,
                              void* d_out, int out_size)
{
    const float* X  = (const float*)d_in[0];
    const float* Wt = (const float*)d_in[1];
    const float* bs = (const float*)d_in[2];
    float* out = (float*)d_out;

    dim3 grid((OW + BX - 1) / BX, (OH + BY - 1) / BY);   // 22 x 256
    conv2d_r8_kernel<<<grid, NT>>>(X, Wt, bs, out);
}